// round 12
// baseline (speedup 1.0000x reference)
#include <cuda_runtime.h>
#include <cstdint>
#include <cstddef>

#define NMAX 100000
#define EMAX 1700000
#define FD 128

typedef unsigned long long ull;
typedef unsigned int uint;

// Scratch — static __device__ globals, referenced only from device code.
__device__ __align__(16) float g_dinv[NMAX];
__device__ __align__(16) float g_h[(size_t)NMAX * FD];   // layer-1 GEMM output
__device__ __align__(16) float g_a[(size_t)NMAX * FD];   // fused kernel output
__device__ int   g_is64;
// CSR
__device__ int   g_cnt[NMAX];
__device__ int   g_fill[NMAX];
__device__ int   g_rowptr[NMAX + 1];
__device__ int   g_bsum[128];
__device__ int   g_boff[128];
__device__ __align__(16) int2 g_epack[EMAX];   // {col, float-bits(norm)}

// ---------------- packed fp32x2 FMA (sm_103a FFMA2) ----------------
__device__ __forceinline__ ull ffma2(ull a, ull b, ull c) {
    ull d;
    asm("fma.rn.f32x2 %0, %1, %2, %3;" : "=l"(d) : "l"(a), "l"(b), "l"(c));
    return d;
}
__device__ __forceinline__ ull dup_f32(float a) {
    ull d;
    asm("mov.b64 %0, {%1, %2};" : "=l"(d) : "f"(a), "f"(a));
    return d;
}
__device__ __forceinline__ float2 unpack_f32x2(ull v) {
    float2 r;
    asm("mov.b64 {%0, %1}, %2;" : "=f"(r.x), "=f"(r.y) : "l"(v));
    return r;
}

// B smem anti-conflict mapping: byte = c*4 + (c>>5)*16, row stride 576 B.
__device__ __forceinline__ int bcol_byte(int c) { return c * 4 + ((c >> 5) << 4); }

// ---------------- zero + dtype detection ----------------
__global__ void zero_detect_kernel(const int* __restrict__ ei32, int E, int n) {
    int i = blockIdx.x * blockDim.x + threadIdx.x;
    if (i < n) { g_dinv[i] = 1.0f; g_cnt[i] = 0; g_fill[i] = 0; }
    if (blockIdx.x == 0) {
        __shared__ int snz;
        if (threadIdx.x == 0) snz = 0;
        __syncthreads();
        int cnt = E < 4096 ? E : 4096, nz = 0;
        for (int j = threadIdx.x; j < cnt; j += blockDim.x) nz |= ei32[2 * j + 1];
        if (nz) atomicOr(&snz, 1);
        __syncthreads();
        if (threadIdx.x == 0) g_is64 = (snz == 0) ? 1 : 0;
    }
}

__device__ __forceinline__ int edge_row(const int* ei32, int E, int e) {
    return g_is64 ? ei32[2 * (size_t)e] : ei32[e];
}
__device__ __forceinline__ int edge_col(const int* ei32, int E, int e) {
    return g_is64 ? ei32[2 * (size_t)E + 2 * (size_t)e] : ei32[(size_t)E + e];
}

// ---------------- degree + CSR build ----------------
__global__ void deg_count_kernel(const int* __restrict__ ei32,
                                 const float* __restrict__ w, int E) {
    int e = blockIdx.x * blockDim.x + threadIdx.x;
    if (e < E) {
        int r = edge_row(ei32, E, e);
        atomicAdd(&g_dinv[r], w[e]);
        atomicAdd(&g_cnt[r], 1);
    }
}

__global__ void dinv_kernel(int n) {
    int i = blockIdx.x * blockDim.x + threadIdx.x;
    if (i < n) {
        float d = g_dinv[i];
        g_dinv[i] = d > 0.0f ? rsqrtf(d) : 0.0f;
    }
}

__global__ void scan_block_kernel(int n) {
    __shared__ int sh[1024];
    int i = blockIdx.x * 1024 + threadIdx.x;
    int v = (i < n) ? g_cnt[i] : 0;
    sh[threadIdx.x] = v;
    __syncthreads();
    for (int off = 1; off < 1024; off <<= 1) {
        int t = (threadIdx.x >= off) ? sh[threadIdx.x - off] : 0;
        __syncthreads();
        sh[threadIdx.x] += t;
        __syncthreads();
    }
    if (i < n) g_rowptr[i] = sh[threadIdx.x] - v;
    if (threadIdx.x == 1023) g_bsum[blockIdx.x] = sh[1023];
}

__global__ void scan_bsum_kernel(int nb) {
    if (threadIdx.x == 0) {
        int acc = 0;
        for (int b = 0; b < nb; b++) { int t = g_bsum[b]; g_boff[b] = acc; acc += t; }
    }
}

__global__ void scan_add_kernel(int n, int E) {
    int i = blockIdx.x * 1024 + threadIdx.x;
    if (i < n) g_rowptr[i] += g_boff[i >> 10];
    if (i == n) g_rowptr[n] = E;
}

__global__ void fill_kernel(const int* __restrict__ ei32,
                            const float* __restrict__ w, int E) {
    int e = blockIdx.x * blockDim.x + threadIdx.x;
    if (e < E) {
        int r = edge_row(ei32, E, e);
        int c = edge_col(ei32, E, e);
        float nm = g_dinv[r] * w[e] * g_dinv[c];
        int idx = g_rowptr[r] + atomicAdd(&g_fill[r], 1);
        g_epack[idx] = make_int2(c, __float_as_int(nm));
    }
}

// ---------------- GEMM-1 (FFMA2, 2 CTAs/SM): g_h = x @ W1 ----------------
__global__ __launch_bounds__(256, 2) void sgemm_kernel_t(
    const float* __restrict__ Aext, const float* __restrict__ W, int n, int relu_in)
{
    __shared__ float As[32][132];
    __shared__ __align__(16) char WsB[32 * 576];

    const int bm  = blockIdx.x * 128;
    const int tid = threadIdx.x;
    const int tm  = (tid >> 4) << 3;
    const int tn  = (tid & 15) << 3;

    ull acc2[8][4];
#pragma unroll
    for (int i = 0; i < 8; i++)
#pragma unroll
        for (int j = 0; j < 4; j++) acc2[i][j] = 0ull;

    char* const wrow0 = WsB + bcol_byte(tn);
    char* const wrow1 = WsB + bcol_byte(tn + 4);

    for (int k0 = 0; k0 < 128; k0 += 32) {
#pragma unroll
        for (int i = 0; i < 4; i++) {
            int t  = tid + i * 256;
            int r  = t >> 3;
            int c4 = (t & 7) << 2;
            int gr = bm + r;
            float4 v = make_float4(0.f, 0.f, 0.f, 0.f);
            if (gr < n) {
                v = *reinterpret_cast<const float4*>(Aext + (size_t)gr * FD + k0 + c4);
                if (relu_in) {
                    v.x = fmaxf(v.x, 0.f); v.y = fmaxf(v.y, 0.f);
                    v.z = fmaxf(v.z, 0.f); v.w = fmaxf(v.w, 0.f);
                }
            }
            As[c4 + 0][r] = v.x; As[c4 + 1][r] = v.y;
            As[c4 + 2][r] = v.z; As[c4 + 3][r] = v.w;
        }
#pragma unroll
        for (int i = 0; i < 4; i++) {
            int t  = tid + i * 256;
            int r  = t >> 5;
            int c4 = (t & 31) << 2;
            float4 v = *reinterpret_cast<const float4*>(W + (size_t)(k0 + r) * FD + c4);
            *reinterpret_cast<float4*>(WsB + r * 576 + bcol_byte(c4)) = v;
        }
        __syncthreads();

#pragma unroll
        for (int k = 0; k < 32; k++) {
            float a[8];
            *reinterpret_cast<float4*>(a)     = *reinterpret_cast<float4*>(&As[k][tm]);
            *reinterpret_cast<float4*>(a + 4) = *reinterpret_cast<float4*>(&As[k][tm + 4]);
            ulonglong2 bq0 = *reinterpret_cast<ulonglong2*>(wrow0 + k * 576);
            ulonglong2 bq1 = *reinterpret_cast<ulonglong2*>(wrow1 + k * 576);
            ull b2[4] = {bq0.x, bq0.y, bq1.x, bq1.y};
            ull ad[8];
#pragma unroll
            for (int i = 0; i < 8; i++) ad[i] = dup_f32(a[i]);
#pragma unroll
            for (int i = 0; i < 8; i++)
#pragma unroll
                for (int j = 0; j < 4; j++)
                    acc2[i][j] = ffma2(ad[i], b2[j], acc2[i][j]);
        }
        __syncthreads();
    }

#pragma unroll
    for (int i = 0; i < 8; i++) {
        int gr = bm + tm + i;
        if (gr < n) {
            float2 p0 = unpack_f32x2(acc2[i][0]);
            float2 p1 = unpack_f32x2(acc2[i][1]);
            float2 p2 = unpack_f32x2(acc2[i][2]);
            float2 p3 = unpack_f32x2(acc2[i][3]);
            *reinterpret_cast<float4*>(g_h + (size_t)gr * FD + tn) =
                make_float4(p0.x, p0.y, p1.x, p1.y);
            *reinterpret_cast<float4*>(g_h + (size_t)gr * FD + tn + 4) =
                make_float4(p2.x, p2.y, p3.x, p3.y);
        }
    }
}

// ---------------- FUSED: g_a = relu(agg(g_h)+b1) @ W2 ---------------------
// Phase A: aggregate 128 rows into transposed As smem (per-warp rows).
// Phase B: FFMA2 mainloop vs W2 in two 64-k chunks. Output -> g_a (NOT g_h:
// other CTAs still gather from g_h in phase A).
#define FS_AST  0
#define FS_W    (128 * 132 * 4)           // 67584
#define FS_TOT  (FS_W + 64 * 576)         // 67584 + 36864 = 104448

__global__ __launch_bounds__(256, 2) void fused_agg_gemm(
    const float* __restrict__ bias, const float* __restrict__ W2, int n)
{
    extern __shared__ char sm[];
    float* const Ast = reinterpret_cast<float*>(sm + FS_AST);   // [k][132]
    char*  const WsB = sm + FS_W;

    const int bm   = blockIdx.x * 128;
    const int tid  = threadIdx.x;
    const int lane = tid & 31;
    const int wid  = tid >> 5;

    // ---- phase A: aggregate + relu into Ast (transposed [k][m]) ----
    {
        float bb[4];
#pragma unroll
        for (int j = 0; j < 4; j++) bb[j] = bias[lane + 32 * j];

        for (int i = 0; i < 16; i++) {
            int local = wid * 16 + i;
            int r = bm + local;
            float acc[4] = {0.f, 0.f, 0.f, 0.f};
            if (r < n) {
                float di = g_dinv[r];
                float s  = di * di;
                const float* hr = g_h + (size_t)r * FD + lane;
#pragma unroll
                for (int j = 0; j < 4; j++) acc[j] = fmaf(s, hr[32 * j], bb[j]);

                int e   = g_rowptr[r];
                int end = g_rowptr[r + 1];
                for (; e + 2 <= end; e += 2) {
                    int2 p0 = g_epack[e];
                    int2 p1 = g_epack[e + 1];
                    float n0 = __int_as_float(p0.y);
                    float n1 = __int_as_float(p1.y);
                    const float* h0 = g_h + (size_t)p0.x * FD + lane;
                    const float* h1 = g_h + (size_t)p1.x * FD + lane;
#pragma unroll
                    for (int j = 0; j < 4; j++) {
                        acc[j] = fmaf(n0, h0[32 * j], acc[j]);
                        acc[j] = fmaf(n1, h1[32 * j], acc[j]);
                    }
                }
                if (e < end) {
                    int2 p0 = g_epack[e];
                    float n0 = __int_as_float(p0.y);
                    const float* h0 = g_h + (size_t)p0.x * FD + lane;
#pragma unroll
                    for (int j = 0; j < 4; j++)
                        acc[j] = fmaf(n0, h0[32 * j], acc[j]);
                }
#pragma unroll
                for (int j = 0; j < 4; j++) acc[j] = fmaxf(acc[j], 0.f);
            }
#pragma unroll
            for (int j = 0; j < 4; j++)
                Ast[(lane + 32 * j) * 132 + local] = acc[j];
        }
    }
    __syncthreads();

    // ---- phase B: FFMA2 GEMM vs W2 ----
    const int tm = (tid >> 4) << 3;
    const int tn = (tid & 15) << 3;

    ull acc2[8][4];
#pragma unroll
    for (int i = 0; i < 8; i++)
#pragma unroll
        for (int j = 0; j < 4; j++) acc2[i][j] = 0ull;

    char* const wrow0 = WsB + bcol_byte(tn);
    char* const wrow1 = WsB + bcol_byte(tn + 4);

    for (int ch = 0; ch < 2; ch++) {
        // stage W2 chunk [64 x 128]
#pragma unroll
        for (int i = 0; i < 8; i++) {
            int t  = tid + i * 256;
            int r  = t >> 5;
            int c4 = (t & 31) << 2;
            float4 v = *reinterpret_cast<const float4*>(
                W2 + (size_t)(ch * 64 + r) * FD + c4);
            *reinterpret_cast<float4*>(WsB + r * 576 + bcol_byte(c4)) = v;
        }
        __syncthreads();

#pragma unroll 8
        for (int k = 0; k < 64; k++) {
            float* arow = Ast + (ch * 64 + k) * 132;
            float a[8];
            *reinterpret_cast<float4*>(a)     = *reinterpret_cast<float4*>(arow + tm);
            *reinterpret_cast<float4*>(a + 4) = *reinterpret_cast<float4*>(arow + tm + 4);
            ulonglong2 bq0 = *reinterpret_cast<ulonglong2*>(wrow0 + k * 576);
            ulonglong2 bq1 = *reinterpret_cast<ulonglong2*>(wrow1 + k * 576);
            ull b2[4] = {bq0.x, bq0.y, bq1.x, bq1.y};
            ull ad[8];
#pragma unroll
            for (int i = 0; i < 8; i++) ad[i] = dup_f32(a[i]);
#pragma unroll
            for (int i = 0; i < 8; i++)
#pragma unroll
                for (int j = 0; j < 4; j++)
                    acc2[i][j] = ffma2(ad[i], b2[j], acc2[i][j]);
        }
        __syncthreads();
    }

#pragma unroll
    for (int i = 0; i < 8; i++) {
        int gr = bm + tm + i;
        if (gr < n) {
            float2 p0 = unpack_f32x2(acc2[i][0]);
            float2 p1 = unpack_f32x2(acc2[i][1]);
            float2 p2 = unpack_f32x2(acc2[i][2]);
            float2 p3 = unpack_f32x2(acc2[i][3]);
            *reinterpret_cast<float4*>(g_a + (size_t)gr * FD + tn) =
                make_float4(p0.x, p0.y, p1.x, p1.y);
            *reinterpret_cast<float4*>(g_a + (size_t)gr * FD + tn + 4) =
                make_float4(p2.x, p2.y, p3.x, p3.y);
        }
    }
}

// ---------------- final aggregation: out = b2 + self + agg(g_a) ----------
__global__ void agg_csr_kernel(const float* __restrict__ bias,
                               float* __restrict__ outExt, int n)
{
    int r    = (blockIdx.x * blockDim.x + threadIdx.x) >> 5;
    int lane = threadIdx.x & 31;
    if (r >= n) return;
    int f4 = lane << 2;

    float di = g_dinv[r];
    float s  = di * di;
    float4 hv = *reinterpret_cast<const float4*>(g_a + (size_t)r * FD + f4);
    float4 bv = *reinterpret_cast<const float4*>(bias + f4);
    float4 acc = make_float4(fmaf(s, hv.x, bv.x), fmaf(s, hv.y, bv.y),
                             fmaf(s, hv.z, bv.z), fmaf(s, hv.w, bv.w));

    int e   = g_rowptr[r];
    int end = g_rowptr[r + 1];
    for (; e + 2 <= end; e += 2) {
        int2 p0 = g_epack[e];
        int2 p1 = g_epack[e + 1];
        float n0 = __int_as_float(p0.y);
        float n1 = __int_as_float(p1.y);
        float4 h0 = *reinterpret_cast<const float4*>(g_a + (size_t)p0.x * FD + f4);
        float4 h1 = *reinterpret_cast<const float4*>(g_a + (size_t)p1.x * FD + f4);
        acc.x = fmaf(n0, h0.x, acc.x); acc.y = fmaf(n0, h0.y, acc.y);
        acc.z = fmaf(n0, h0.z, acc.z); acc.w = fmaf(n0, h0.w, acc.w);
        acc.x = fmaf(n1, h1.x, acc.x); acc.y = fmaf(n1, h1.y, acc.y);
        acc.z = fmaf(n1, h1.z, acc.z); acc.w = fmaf(n1, h1.w, acc.w);
    }
    if (e < end) {
        int2 p0 = g_epack[e];
        float n0 = __int_as_float(p0.y);
        float4 h0 = *reinterpret_cast<const float4*>(g_a + (size_t)p0.x * FD + f4);
        acc.x = fmaf(n0, h0.x, acc.x); acc.y = fmaf(n0, h0.y, acc.y);
        acc.z = fmaf(n0, h0.z, acc.z); acc.w = fmaf(n0, h0.w, acc.w);
    }

    *reinterpret_cast<float4*>(outExt + (size_t)r * FD + f4) = acc;
}

// ---------------- launch ----------------
extern "C" void kernel_launch(void* const* d_in, const int* in_sizes, int n_in,
                              void* d_out, int out_size)
{
    const float* x    = (const float*)d_in[0];
    const int*   ei32 = (const int*)d_in[1];
    const float* ew   = (const float*)d_in[2];
    const float* W1   = (const float*)d_in[3];
    const float* b1   = (const float*)d_in[4];
    const float* W2   = (const float*)d_in[5];
    const float* b2   = (const float*)d_in[6];
    float* out = (float*)d_out;

    const int n = in_sizes[0] / FD;
    const int E = in_sizes[2];

    cudaFuncSetAttribute(fused_agg_gemm,
                         cudaFuncAttributeMaxDynamicSharedMemorySize, FS_TOT);

    const int gemm_blocks = (n + 127) / 128;
    const int agg_blocks  = (n * 32 + 255) / 256;
    const int scan_blocks = (n + 1023) / 1024;

    zero_detect_kernel<<<(n + 255) / 256, 256>>>(ei32, E, n);       // 0
    deg_count_kernel<<<(E + 255) / 256, 256>>>(ei32, ew, E);        // 1
    dinv_kernel<<<(n + 255) / 256, 256>>>(n);                       // 2
    sgemm_kernel_t<<<gemm_blocks, 256>>>(x, W1, n, 0);              // 3 <- profiled
    scan_block_kernel<<<scan_blocks, 1024>>>(n);                    // 4
    scan_bsum_kernel<<<1, 32>>>(scan_blocks);                       // 5
    scan_add_kernel<<<(n + 1024) / 1024, 1024>>>(n, E);             // 6
    fill_kernel<<<(E + 255) / 256, 256>>>(ei32, ew, E);             // 7
    fused_agg_gemm<<<gemm_blocks, 256, FS_TOT>>>(b1, W2, n);        // 8
    agg_csr_kernel<<<agg_blocks, 256>>>(b2, out, n);                // 9
}